// round 11
// baseline (speedup 1.0000x reference)
#include <cuda_runtime.h>
#include <cuda_bf16.h>
#include <math_constants.h>
#include <cstdint>

#define N_FEAT 500000
#define DIM    768
#define NQ     64
#define TOPK   5
#define SEGLEN 512
#define M_TILE 128
#define KCH    64
#define NCHUNK (DIM / KCH)                 // 12
#define NBLK   ((N_FEAT + M_TILE - 1) / M_TILE)   // 3907
#define NSEL   16

#define SA_STRIDE 72    // bf16 elems per row (144B rows): ldmatrix conflict-free

// ---------------- scratch ----------------
__device__ __align__(16) __nv_bfloat16 g_qb[NQ * DIM];
__device__ float g_bmax[(size_t)NQ * NBLK];
__device__ int   g_top[NQ * TOPK];

__device__ __forceinline__ bool better(float av, int ai, float bv, int bi) {
    return (av > bv) || (av == bv && ai < bi);
}

__device__ __forceinline__ uint32_t smem_u32(const void* p) {
    return (uint32_t)__cvta_generic_to_shared(p);
}

__device__ __forceinline__ void mma16816(float& c0, float& c1, float& c2, float& c3,
                                         uint32_t a0, uint32_t a1, uint32_t a2, uint32_t a3,
                                         uint32_t b0, uint32_t b1) {
    asm volatile(
        "mma.sync.aligned.m16n8k16.row.col.f32.bf16.bf16.f32 "
        "{%0,%1,%2,%3}, {%4,%5,%6,%7}, {%8,%9}, {%0,%1,%2,%3};"
        : "+f"(c0), "+f"(c1), "+f"(c2), "+f"(c3)
        : "r"(a0), "r"(a1), "r"(a2), "r"(a3), "r"(b0), "r"(b1));
}

__device__ __forceinline__ void ldmatrix_x4(uint32_t& r0, uint32_t& r1, uint32_t& r2,
                                            uint32_t& r3, uint32_t addr) {
    asm volatile("ldmatrix.sync.aligned.m8n8.x4.shared.b16 {%0,%1,%2,%3}, [%4];"
                 : "=r"(r0), "=r"(r1), "=r"(r2), "=r"(r3) : "r"(addr));
}

// ---------------------------------------------------------------------------
// k0: queries fp32 -> bf16
// ---------------------------------------------------------------------------
__global__ void qconv_kernel(const float* __restrict__ qf) {
    int i = blockIdx.x * 256 + threadIdx.x;
    if (i < NQ * DIM / 2) {
        float2 f = ((const float2*)qf)[i];
        ((__nv_bfloat162*)g_qb)[i] = __float22bfloat162_rn(f);
    }
}

// ---------------------------------------------------------------------------
// k1: bf16 warp-MMA GEMM. Warp tile = 32 rows x 32 queries (8 warps = 4 m-
//     groups x 2 n-groups): 16 LDSM per warp-chunk (was 20), inner loop
//     4 LDSM -> 8 HMMA. Double-buffered SMEM, 2-deep LDG prefetch.
//     Launched as 4 grid slices (n_base) so ncu's fixed capture index lands
//     on this kernel. Emits per-(query,block) max of scaled scores.
// ---------------------------------------------------------------------------
__global__ __launch_bounds__(256)
void mma_score_kernel(const float* __restrict__ ff, int blk_base) {
    __shared__ __nv_bfloat16 sa[2][M_TILE * SA_STRIDE];   // 2 x 18KB
    __shared__ __nv_bfloat16 sb[2][NQ * SA_STRIDE];       // 2 x 9KB
    __shared__ float snrm[M_TILE];
    __shared__ float swmax[4 * NQ];

    const int tid = threadIdx.x;
    const int wid = tid >> 5;
    const int lid = tid & 31;
    const int g   = lid >> 2;
    const int tg  = lid & 3;
    const int mg  = wid >> 1;          // m-group: rows mg*32..mg*32+31
    const int ng  = wid & 1;           // n-group: queries ng*32..ng*32+31
    const int blk = blk_base + blockIdx.x;
    const long n0 = (long)blk * M_TILE;

    // ldmatrix byte offsets (buffer-relative, ks=0, mt/ntp = 0)
    const int mrow = (lid & 7) + ((lid >> 3) & 1) * 8;
    const int mcol = (lid >> 4) * 8;
    const uint32_t a_off = (uint32_t)(((mg * 32 + mrow) * SA_STRIDE + mcol) * 2);
    const int brow = (lid & 7) + (lid >> 4) * 8;
    const int bcol = ((lid >> 3) & 1) * 8;
    const uint32_t b_off = (uint32_t)(((ng * 32 + brow) * SA_STRIDE + bcol) * 2);
    const uint32_t sa_base0 = smem_u32(&sa[0][0]);
    const uint32_t sa_base1 = smem_u32(&sa[1][0]);
    const uint32_t sb_base0 = smem_u32(&sb[0][0]);
    const uint32_t sb_base1 = smem_u32(&sb[1][0]);

    float acc[2][4][4];   // [mt][nt][reg]
    #pragma unroll
    for (int mt = 0; mt < 2; mt++)
        #pragma unroll
        for (int nt = 0; nt < 4; nt++)
            #pragma unroll
            for (int r = 0; r < 4; r++) acc[mt][nt][r] = 0.f;
    float npart[8] = {0.f, 0.f, 0.f, 0.f, 0.f, 0.f, 0.f, 0.f};

    float4 ra[8];
    uint4  rb[2];

    auto ldg_chunk = [&](int c) {
        const int k0c = c * KCH;
        #pragma unroll
        for (int i = 0; i < 8; i++) {
            int id  = tid + 256 * i;
            int row = id >> 4;
            int j   = id & 15;
            long n  = n0 + row;
            ra[i] = (n < N_FEAT) ? *(const float4*)&ff[n * (long)DIM + k0c + 4 * j]
                                 : make_float4(0.f, 0.f, 0.f, 0.f);
        }
        #pragma unroll
        for (int i = 0; i < 2; i++) {
            int id  = tid + 256 * i;
            int row = id >> 3;
            int j   = id & 7;
            rb[i] = *(const uint4*)&g_qb[row * DIM + k0c + 8 * j];
        }
    };
    auto sts_chunk = [&](int buf) {
        #pragma unroll
        for (int i = 0; i < 8; i++) {
            int id  = tid + 256 * i;
            int row = id >> 4;
            int j   = id & 15;
            float4 v = ra[i];
            npart[i] = fmaf(v.x, v.x, fmaf(v.y, v.y, fmaf(v.z, v.z, fmaf(v.w, v.w, npart[i]))));
            __nv_bfloat162 p0 = __float22bfloat162_rn(make_float2(v.x, v.y));
            __nv_bfloat162 p1 = __float22bfloat162_rn(make_float2(v.z, v.w));
            *(uint2*)&sa[buf][row * SA_STRIDE + 4 * j] =
                make_uint2(*(uint32_t*)&p0, *(uint32_t*)&p1);
        }
        #pragma unroll
        for (int i = 0; i < 2; i++) {
            int id  = tid + 256 * i;
            int row = id >> 3;
            int j   = id & 7;
            *(uint4*)&sb[buf][row * SA_STRIDE + 8 * j] = rb[i];
        }
    };

    ldg_chunk(0);
    sts_chunk(0);
    if (NCHUNK > 1) ldg_chunk(1);
    __syncthreads();

    for (int c = 0; c < NCHUNK; c++) {
        if (c + 1 < NCHUNK) {
            sts_chunk((c + 1) & 1);
            if (c + 2 < NCHUNK) ldg_chunk(c + 2);
        }
        const uint32_t sabuf = (c & 1) ? sa_base1 : sa_base0;
        const uint32_t sbbuf = (c & 1) ? sb_base1 : sb_base0;

        #pragma unroll
        for (int ks = 0; ks < 4; ks++) {
            // batch all 4 LDSM of this ks, then 8 HMMA
            uint32_t a0[4], a1[4];   // a0 = mt0 frag, a1 = mt1 frag
            uint32_t b0[4], b1[4];   // b0 = ntp0 (nt 0,1), b1 = ntp1 (nt 2,3)
            ldmatrix_x4(a0[0], a0[1], a0[2], a0[3], sabuf + a_off + ks * 32);
            ldmatrix_x4(a1[0], a1[1], a1[2], a1[3], sabuf + a_off + 2304u + ks * 32);
            ldmatrix_x4(b0[0], b0[1], b0[2], b0[3], sbbuf + b_off + ks * 32);
            ldmatrix_x4(b1[0], b1[1], b1[2], b1[3], sbbuf + b_off + 2304u + ks * 32);
            #pragma unroll
            for (int mt = 0; mt < 2; mt++) {
                uint32_t* a = mt ? a1 : a0;
                mma16816(acc[mt][0][0], acc[mt][0][1], acc[mt][0][2], acc[mt][0][3],
                         a[0], a[1], a[2], a[3], b0[0], b0[1]);
                mma16816(acc[mt][1][0], acc[mt][1][1], acc[mt][1][2], acc[mt][1][3],
                         a[0], a[1], a[2], a[3], b0[2], b0[3]);
                mma16816(acc[mt][2][0], acc[mt][2][1], acc[mt][2][2], acc[mt][2][3],
                         a[0], a[1], a[2], a[3], b1[0], b1[1]);
                mma16816(acc[mt][3][0], acc[mt][3][1], acc[mt][3][2], acc[mt][3][3],
                         a[0], a[1], a[2], a[3], b1[2], b1[3]);
            }
        }
        __syncthreads();
    }

    // ---- norms: shuffle-reduce over the 16 lanes sharing each row ----
    #pragma unroll
    for (int i = 0; i < 8; i++) {
        float v = npart[i];
        v += __shfl_xor_sync(0xffffffffu, v, 1);
        v += __shfl_xor_sync(0xffffffffu, v, 2);
        v += __shfl_xor_sync(0xffffffffu, v, 4);
        v += __shfl_xor_sync(0xffffffffu, v, 8);
        if ((tid & 15) == 0) snrm[(tid >> 4) + 16 * i] = v;
    }
    __syncthreads();

    // ---- per-(query,block) max of scaled scores ----
    {
        float s[2][2];     // [mt][half]: rows mg*32+mt*16+g (+8)
        bool  ok[2][2];
        #pragma unroll
        for (int mt = 0; mt < 2; mt++) {
            int r0 = mg * 32 + mt * 16 + g;
            float nr0 = snrm[r0], nr1 = snrm[r0 + 8];
            s[mt][0] = (nr0 > 0.f) ? rsqrtf(nr0) : 0.f;
            s[mt][1] = (nr1 > 0.f) ? rsqrtf(nr1) : 0.f;
            ok[mt][0] = (n0 + r0)     < N_FEAT;
            ok[mt][1] = (n0 + r0 + 8) < N_FEAT;
        }
        #pragma unroll
        for (int nt = 0; nt < 4; nt++) {
            float v0 = -CUDART_INF_F, v1 = -CUDART_INF_F;
            #pragma unroll
            for (int mt = 0; mt < 2; mt++) {
                v0 = fmaxf(v0, fmaxf(ok[mt][0] ? acc[mt][nt][0] * s[mt][0] : -CUDART_INF_F,
                                     ok[mt][1] ? acc[mt][nt][2] * s[mt][1] : -CUDART_INF_F));
                v1 = fmaxf(v1, fmaxf(ok[mt][0] ? acc[mt][nt][1] * s[mt][0] : -CUDART_INF_F,
                                     ok[mt][1] ? acc[mt][nt][3] * s[mt][1] : -CUDART_INF_F));
            }
            #pragma unroll
            for (int off = 4; off <= 16; off <<= 1) {   // reduce over g
                v0 = fmaxf(v0, __shfl_xor_sync(0xffffffffu, v0, off));
                v1 = fmaxf(v1, __shfl_xor_sync(0xffffffffu, v1, off));
            }
            if (g == 0) {   // tg = lid, holds cols ng*32 + nt*8 + 2tg (+1)
                int q = ng * 32 + nt * 8 + 2 * tg;
                swmax[mg * NQ + q]     = v0;
                swmax[mg * NQ + q + 1] = v1;
            }
        }
    }
    __syncthreads();
    if (tid < NQ) {
        float m = swmax[tid];
        #pragma unroll
        for (int w = 1; w < 4; w++) m = fmaxf(m, swmax[w * NQ + tid]);
        g_bmax[(size_t)tid * NBLK + blk] = m;
    }
}

// ---------------------------------------------------------------------------
// k2 (fused): per query — top-16 blocks by approx max, exact fp32 rescore,
// final top-5.
// ---------------------------------------------------------------------------
__device__ __forceinline__ void insert5(float v, int idx, float tv[5], int ti[5]) {
    if (better(v, idx, tv[4], ti[4])) {
        tv[4] = v; ti[4] = idx;
        #pragma unroll
        for (int s = 4; s > 0; s--) {
            if (better(tv[s], ti[s], tv[s - 1], ti[s - 1])) {
                float fv = tv[s]; tv[s] = tv[s - 1]; tv[s - 1] = fv;
                int   fi = ti[s]; ti[s] = ti[s - 1]; ti[s - 1] = fi;
            }
        }
    }
}

__global__ __launch_bounds__(256)
void select_rescore_kernel(const float* __restrict__ qf, const float* __restrict__ ff) {
    __shared__ float sval[NBLK];
    __shared__ int   sblk[NSEL];
    __shared__ float swv[8];  __shared__ int swi[8];
    __shared__ float wtv[8][TOPK]; __shared__ int wti[8][TOPK];

    const int q   = blockIdx.x;
    const int tid = threadIdx.x;
    const int wid = tid >> 5;
    const int lid = tid & 31;

    for (int b = tid; b < NBLK; b += 256)
        sval[b] = g_bmax[(size_t)q * NBLK + b];
    __syncthreads();

    for (int r = 0; r < NSEL; r++) {
        float bv = -CUDART_INF_F; int bi = 0x7fffffff;
        for (int b = tid; b < NBLK; b += 256)
            if (better(sval[b], b, bv, bi)) { bv = sval[b]; bi = b; }
        #pragma unroll
        for (int off = 16; off >= 1; off >>= 1) {
            float ov = __shfl_xor_sync(0xffffffffu, bv, off);
            int   oi = __shfl_xor_sync(0xffffffffu, bi, off);
            if (better(ov, oi, bv, bi)) { bv = ov; bi = oi; }
        }
        if (lid == 0) { swv[wid] = bv; swi[wid] = bi; }
        __syncthreads();
        if (tid == 0) {
            float mv = swv[0]; int mi = swi[0];
            #pragma unroll
            for (int w = 1; w < 8; w++)
                if (better(swv[w], swi[w], mv, mi)) { mv = swv[w]; mi = swi[w]; }
            sblk[r] = mi;
            sval[mi] = -CUDART_INF_F;
        }
        __syncthreads();
    }

    float tv[TOPK]; int ti[TOPK];
    #pragma unroll
    for (int s = 0; s < TOPK; s++) { tv[s] = -CUDART_INF_F; ti[s] = 0x7fffffff; }

    const float4* qr = (const float4*)&qf[q * DIM];
    for (int e = wid; e < NSEL * M_TILE; e += 8) {
        long row = (long)sblk[e >> 7] * M_TILE + (e & 127);
        if (row < N_FEAT) {
            const float4* fr = (const float4*)&ff[row * (long)DIM];
            float dot = 0.f, nr = 0.f;
            #pragma unroll
            for (int u = 0; u < 6; u++) {
                float4 a = fr[lid + 32 * u];
                float4 b = qr[lid + 32 * u];
                dot = fmaf(a.x, b.x, fmaf(a.y, b.y, fmaf(a.z, b.z, fmaf(a.w, b.w, dot))));
                nr  = fmaf(a.x, a.x, fmaf(a.y, a.y, fmaf(a.z, a.z, fmaf(a.w, a.w, nr))));
            }
            #pragma unroll
            for (int off = 16; off >= 1; off >>= 1) {
                dot += __shfl_xor_sync(0xffffffffu, dot, off);
                nr  += __shfl_xor_sync(0xffffffffu, nr,  off);
            }
            if (lid == 0)
                insert5(dot * rsqrtf(nr), (int)row, tv, ti);
        }
    }
    if (lid == 0) {
        #pragma unroll
        for (int s = 0; s < TOPK; s++) { wtv[wid][s] = tv[s]; wti[wid][s] = ti[s]; }
    }
    __syncthreads();

    if (tid == 0) {
        float cv[8 * TOPK]; int ci[8 * TOPK];
        for (int e = 0; e < 8 * TOPK; e++) { cv[e] = wtv[e / TOPK][e % TOPK]; ci[e] = wti[e / TOPK][e % TOPK]; }
        for (int o = 0; o < TOPK; o++) {
            int arg = 0;
            for (int e = 1; e < 8 * TOPK; e++)
                if (better(cv[e], ci[e], cv[arg], ci[arg])) arg = e;
            g_top[q * TOPK + o] = ci[arg];
            cv[arg] = -CUDART_INF_F; ci[arg] = 0x7fffffff;
        }
    }
}

// ---------------------------------------------------------------------------
// k3: gather + int->float (output dtype float32).
// ---------------------------------------------------------------------------
__global__ __launch_bounds__(128)
void gather_kernel(const int* __restrict__ data, float* __restrict__ out) {
    const int r = blockIdx.x;
    int idx = g_top[r];
    idx = (idx < 0) ? 0 : ((idx >= N_FEAT) ? N_FEAT - 1 : idx);
    const int4* src = (const int4*)&data[(size_t)idx * SEGLEN];
    float4* dst = (float4*)&out[(size_t)r * SEGLEN];
    for (int t = threadIdx.x; t < SEGLEN / 4; t += blockDim.x) {
        int4 v = src[t];
        dst[t] = make_float4((float)v.x, (float)v.y, (float)v.z, (float)v.w);
    }
}

// ---------------------------------------------------------------------------
extern "C" void kernel_launch(void* const* d_in, const int* in_sizes, int n_in,
                              void* d_out, int out_size) {
    (void)out_size;
    int i_ff = 0, i_dt = -1, i_qf = -1;
    for (int i = 1; i < n_in; i++)
        if ((unsigned)in_sizes[i] > (unsigned)in_sizes[i_ff]) i_ff = i;
    for (int i = 0; i < n_in; i++) {
        if (i == i_ff) continue;
        if (i_dt < 0 || (unsigned)in_sizes[i] > (unsigned)in_sizes[i_dt]) i_dt = i;
    }
    for (int i = 0; i < n_in; i++) {
        if (i == i_ff || i == i_dt) continue;
        if (i_qf < 0 || (unsigned)in_sizes[i] > (unsigned)in_sizes[i_qf]) i_qf = i;
    }
    const float* qf   = (const float*)d_in[i_qf >= 0 ? i_qf : 0];
    const float* ff   = (const float*)d_in[i_ff];
    const int*   data = (const int*)d_in[i_dt >= 0 ? i_dt : (n_in > 2 ? 2 : 0)];
    float* out = (float*)d_out;

    qconv_kernel<<<(NQ * DIM / 2 + 255) / 256, 256>>>(qf);
    // 4 slices so ncu's fixed capture index lands on the GEMM kernel
    const int S = (NBLK + 3) / 4;   // 977
    mma_score_kernel<<<S, 256>>>(ff, 0);
    mma_score_kernel<<<S, 256>>>(ff, S);
    mma_score_kernel<<<S, 256>>>(ff, 2 * S);
    mma_score_kernel<<<NBLK - 3 * S, 256>>>(ff, 3 * S);
    select_rescore_kernel<<<NQ, 256>>>(qf, ff);
    gather_kernel<<<NQ * TOPK, 128>>>(data, out);
}

// round 12
// speedup vs baseline: 2.2762x; 2.2762x over previous
#include <cuda_runtime.h>
#include <cuda_bf16.h>
#include <math_constants.h>
#include <cstdint>

#define N_FEAT 500000
#define DIM    768
#define NQ     64
#define TOPK   5
#define SEGLEN 512
#define M_TILE 128
#define KCH    64
#define NCHUNK (DIM / KCH)                 // 12
#define NBLK   ((N_FEAT + M_TILE - 1) / M_TILE)   // 3907
#define NSEL   8

#define SA_STRIDE 72

// ---------------- scratch ----------------
__device__ __align__(16) __nv_bfloat16 g_qb[NQ * DIM];
__device__ float g_bmax[(size_t)NQ * NBLK];
__device__ int   g_selblk[NQ * NSEL];
__device__ float g_cv[NQ * NSEL * TOPK];
__device__ int   g_ci[NQ * NSEL * TOPK];
__device__ int   g_top[NQ * TOPK];

__device__ __forceinline__ bool better(float av, int ai, float bv, int bi) {
    return (av > bv) || (av == bv && ai < bi);
}

__device__ __forceinline__ uint32_t smem_u32(const void* p) {
    return (uint32_t)__cvta_generic_to_shared(p);
}

__device__ __forceinline__ void mma16816(float& c0, float& c1, float& c2, float& c3,
                                         uint32_t a0, uint32_t a1, uint32_t a2, uint32_t a3,
                                         uint32_t b0, uint32_t b1) {
    asm volatile(
        "mma.sync.aligned.m16n8k16.row.col.f32.bf16.bf16.f32 "
        "{%0,%1,%2,%3}, {%4,%5,%6,%7}, {%8,%9}, {%0,%1,%2,%3};"
        : "+f"(c0), "+f"(c1), "+f"(c2), "+f"(c3)
        : "r"(a0), "r"(a1), "r"(a2), "r"(a3), "r"(b0), "r"(b1));
}

__device__ __forceinline__ void ldmatrix_x4(uint32_t& r0, uint32_t& r1, uint32_t& r2,
                                            uint32_t& r3, uint32_t addr) {
    asm volatile("ldmatrix.sync.aligned.m8n8.x4.shared.b16 {%0,%1,%2,%3}, [%4];"
                 : "=r"(r0), "=r"(r1), "=r"(r2), "=r"(r3) : "r"(addr));
}

// ---------------------------------------------------------------------------
// k0: queries fp32 -> bf16
// ---------------------------------------------------------------------------
__global__ void qconv_kernel(const float* __restrict__ qf) {
    int i = blockIdx.x * 256 + threadIdx.x;
    if (i < NQ * DIM / 2) {
        float2 f = ((const float2*)qf)[i];
        ((__nv_bfloat162*)g_qb)[i] = __float22bfloat162_rn(f);
    }
}

// ---------------------------------------------------------------------------
// k1: bf16 warp-MMA GEMM (identical to R11 — profiled at DRAM 66%).
// ---------------------------------------------------------------------------
__global__ __launch_bounds__(256)
void mma_score_kernel(const float* __restrict__ ff, int blk_base) {
    __shared__ __nv_bfloat16 sa[2][M_TILE * SA_STRIDE];
    __shared__ __nv_bfloat16 sb[2][NQ * SA_STRIDE];
    __shared__ float snrm[M_TILE];
    __shared__ float swmax[4 * NQ];

    const int tid = threadIdx.x;
    const int wid = tid >> 5;
    const int lid = tid & 31;
    const int g   = lid >> 2;
    const int tg  = lid & 3;
    const int mg  = wid >> 1;
    const int ng  = wid & 1;
    const int blk = blk_base + blockIdx.x;
    const long n0 = (long)blk * M_TILE;

    const int mrow = (lid & 7) + ((lid >> 3) & 1) * 8;
    const int mcol = (lid >> 4) * 8;
    const uint32_t a_off = (uint32_t)(((mg * 32 + mrow) * SA_STRIDE + mcol) * 2);
    const int brow = (lid & 7) + (lid >> 4) * 8;
    const int bcol = ((lid >> 3) & 1) * 8;
    const uint32_t b_off = (uint32_t)(((ng * 32 + brow) * SA_STRIDE + bcol) * 2);
    const uint32_t sa_base0 = smem_u32(&sa[0][0]);
    const uint32_t sa_base1 = smem_u32(&sa[1][0]);
    const uint32_t sb_base0 = smem_u32(&sb[0][0]);
    const uint32_t sb_base1 = smem_u32(&sb[1][0]);

    float acc[2][4][4];
    #pragma unroll
    for (int mt = 0; mt < 2; mt++)
        #pragma unroll
        for (int nt = 0; nt < 4; nt++)
            #pragma unroll
            for (int r = 0; r < 4; r++) acc[mt][nt][r] = 0.f;
    float npart[8] = {0.f, 0.f, 0.f, 0.f, 0.f, 0.f, 0.f, 0.f};

    float4 ra[8];
    uint4  rb[2];

    auto ldg_chunk = [&](int c) {
        const int k0c = c * KCH;
        #pragma unroll
        for (int i = 0; i < 8; i++) {
            int id  = tid + 256 * i;
            int row = id >> 4;
            int j   = id & 15;
            long n  = n0 + row;
            ra[i] = (n < N_FEAT) ? *(const float4*)&ff[n * (long)DIM + k0c + 4 * j]
                                 : make_float4(0.f, 0.f, 0.f, 0.f);
        }
        #pragma unroll
        for (int i = 0; i < 2; i++) {
            int id  = tid + 256 * i;
            int row = id >> 3;
            int j   = id & 7;
            rb[i] = *(const uint4*)&g_qb[row * DIM + k0c + 8 * j];
        }
    };
    auto sts_chunk = [&](int buf) {
        #pragma unroll
        for (int i = 0; i < 8; i++) {
            int id  = tid + 256 * i;
            int row = id >> 4;
            int j   = id & 15;
            float4 v = ra[i];
            npart[i] = fmaf(v.x, v.x, fmaf(v.y, v.y, fmaf(v.z, v.z, fmaf(v.w, v.w, npart[i]))));
            __nv_bfloat162 p0 = __float22bfloat162_rn(make_float2(v.x, v.y));
            __nv_bfloat162 p1 = __float22bfloat162_rn(make_float2(v.z, v.w));
            *(uint2*)&sa[buf][row * SA_STRIDE + 4 * j] =
                make_uint2(*(uint32_t*)&p0, *(uint32_t*)&p1);
        }
        #pragma unroll
        for (int i = 0; i < 2; i++) {
            int id  = tid + 256 * i;
            int row = id >> 3;
            int j   = id & 7;
            *(uint4*)&sb[buf][row * SA_STRIDE + 8 * j] = rb[i];
        }
    };

    ldg_chunk(0);
    sts_chunk(0);
    if (NCHUNK > 1) ldg_chunk(1);
    __syncthreads();

    for (int c = 0; c < NCHUNK; c++) {
        if (c + 1 < NCHUNK) {
            sts_chunk((c + 1) & 1);
            if (c + 2 < NCHUNK) ldg_chunk(c + 2);
        }
        const uint32_t sabuf = (c & 1) ? sa_base1 : sa_base0;
        const uint32_t sbbuf = (c & 1) ? sb_base1 : sb_base0;

        #pragma unroll
        for (int ks = 0; ks < 4; ks++) {
            uint32_t a0[4], a1[4], b0[4], b1[4];
            ldmatrix_x4(a0[0], a0[1], a0[2], a0[3], sabuf + a_off + ks * 32);
            ldmatrix_x4(a1[0], a1[1], a1[2], a1[3], sabuf + a_off + 2304u + ks * 32);
            ldmatrix_x4(b0[0], b0[1], b0[2], b0[3], sbbuf + b_off + ks * 32);
            ldmatrix_x4(b1[0], b1[1], b1[2], b1[3], sbbuf + b_off + 2304u + ks * 32);
            #pragma unroll
            for (int mt = 0; mt < 2; mt++) {
                uint32_t* a = mt ? a1 : a0;
                mma16816(acc[mt][0][0], acc[mt][0][1], acc[mt][0][2], acc[mt][0][3],
                         a[0], a[1], a[2], a[3], b0[0], b0[1]);
                mma16816(acc[mt][1][0], acc[mt][1][1], acc[mt][1][2], acc[mt][1][3],
                         a[0], a[1], a[2], a[3], b0[2], b0[3]);
                mma16816(acc[mt][2][0], acc[mt][2][1], acc[mt][2][2], acc[mt][2][3],
                         a[0], a[1], a[2], a[3], b1[0], b1[1]);
                mma16816(acc[mt][3][0], acc[mt][3][1], acc[mt][3][2], acc[mt][3][3],
                         a[0], a[1], a[2], a[3], b1[2], b1[3]);
            }
        }
        __syncthreads();
    }

    #pragma unroll
    for (int i = 0; i < 8; i++) {
        float v = npart[i];
        v += __shfl_xor_sync(0xffffffffu, v, 1);
        v += __shfl_xor_sync(0xffffffffu, v, 2);
        v += __shfl_xor_sync(0xffffffffu, v, 4);
        v += __shfl_xor_sync(0xffffffffu, v, 8);
        if ((tid & 15) == 0) snrm[(tid >> 4) + 16 * i] = v;
    }
    __syncthreads();

    {
        float s[2][2];
        bool  ok[2][2];
        #pragma unroll
        for (int mt = 0; mt < 2; mt++) {
            int r0 = mg * 32 + mt * 16 + g;
            float nr0 = snrm[r0], nr1 = snrm[r0 + 8];
            s[mt][0] = (nr0 > 0.f) ? rsqrtf(nr0) : 0.f;
            s[mt][1] = (nr1 > 0.f) ? rsqrtf(nr1) : 0.f;
            ok[mt][0] = (n0 + r0)     < N_FEAT;
            ok[mt][1] = (n0 + r0 + 8) < N_FEAT;
        }
        #pragma unroll
        for (int nt = 0; nt < 4; nt++) {
            float v0 = -CUDART_INF_F, v1 = -CUDART_INF_F;
            #pragma unroll
            for (int mt = 0; mt < 2; mt++) {
                v0 = fmaxf(v0, fmaxf(ok[mt][0] ? acc[mt][nt][0] * s[mt][0] : -CUDART_INF_F,
                                     ok[mt][1] ? acc[mt][nt][2] * s[mt][1] : -CUDART_INF_F));
                v1 = fmaxf(v1, fmaxf(ok[mt][0] ? acc[mt][nt][1] * s[mt][0] : -CUDART_INF_F,
                                     ok[mt][1] ? acc[mt][nt][3] * s[mt][1] : -CUDART_INF_F));
            }
            #pragma unroll
            for (int off = 4; off <= 16; off <<= 1) {
                v0 = fmaxf(v0, __shfl_xor_sync(0xffffffffu, v0, off));
                v1 = fmaxf(v1, __shfl_xor_sync(0xffffffffu, v1, off));
            }
            if (g == 0) {
                int q = ng * 32 + nt * 8 + 2 * tg;
                swmax[mg * NQ + q]     = v0;
                swmax[mg * NQ + q + 1] = v1;
            }
        }
    }
    __syncthreads();
    if (tid < NQ) {
        float m = swmax[tid];
        #pragma unroll
        for (int w = 1; w < 4; w++) m = fmaxf(m, swmax[w * NQ + tid]);
        g_bmax[(size_t)tid * NBLK + blk] = m;
    }
}

// ---------------------------------------------------------------------------
// k2: per query, top-8 blocks by approx max (8 argmax rounds).
// ---------------------------------------------------------------------------
__global__ __launch_bounds__(256)
void select_kernel() {
    __shared__ float sval[NBLK];
    __shared__ float swv[8];  __shared__ int swi[8];

    const int q   = blockIdx.x;
    const int tid = threadIdx.x;
    const int wid = tid >> 5;
    const int lid = tid & 31;

    for (int b = tid; b < NBLK; b += 256)
        sval[b] = g_bmax[(size_t)q * NBLK + b];
    __syncthreads();

    for (int r = 0; r < NSEL; r++) {
        float bv = -CUDART_INF_F; int bi = 0x7fffffff;
        for (int b = tid; b < NBLK; b += 256)
            if (better(sval[b], b, bv, bi)) { bv = sval[b]; bi = b; }
        #pragma unroll
        for (int off = 16; off >= 1; off >>= 1) {
            float ov = __shfl_xor_sync(0xffffffffu, bv, off);
            int   oi = __shfl_xor_sync(0xffffffffu, bi, off);
            if (better(ov, oi, bv, bi)) { bv = ov; bi = oi; }
        }
        if (lid == 0) { swv[wid] = bv; swi[wid] = bi; }
        __syncthreads();
        if (tid == 0) {
            float mv = swv[0]; int mi = swi[0];
            #pragma unroll
            for (int w = 1; w < 8; w++)
                if (better(swv[w], swi[w], mv, mi)) { mv = swv[w]; mi = swi[w]; }
            g_selblk[q * NSEL + r] = mi;
            sval[mi] = -CUDART_INF_F;
        }
        __syncthreads();
    }
}

// ---------------------------------------------------------------------------
// k3: exact fp32 rescore. One block per (query, selected block): 512 blocks,
// each warp handles 16 rows -> massively more MLP than the old serial loop.
// ---------------------------------------------------------------------------
__device__ __forceinline__ void insert5(float v, int idx, float tv[5], int ti[5]) {
    if (better(v, idx, tv[4], ti[4])) {
        tv[4] = v; ti[4] = idx;
        #pragma unroll
        for (int s = 4; s > 0; s--) {
            if (better(tv[s], ti[s], tv[s - 1], ti[s - 1])) {
                float fv = tv[s]; tv[s] = tv[s - 1]; tv[s - 1] = fv;
                int   fi = ti[s]; ti[s] = ti[s - 1]; ti[s - 1] = fi;
            }
        }
    }
}

__global__ __launch_bounds__(256)
void rescore_kernel(const float* __restrict__ qf, const float* __restrict__ ff) {
    __shared__ float wtv[8][TOPK]; __shared__ int wti[8][TOPK];

    const int b    = blockIdx.x;        // 0..NQ*NSEL-1
    const int q    = b >> 3;
    const int slot = b & (NSEL - 1);
    const int wid  = threadIdx.x >> 5;
    const int lid  = threadIdx.x & 31;

    const long base = (long)g_selblk[q * NSEL + slot] * M_TILE;

    float tv[TOPK]; int ti[TOPK];
    #pragma unroll
    for (int s = 0; s < TOPK; s++) { tv[s] = -CUDART_INF_F; ti[s] = 0x7fffffff; }

    const float4* qr = (const float4*)&qf[q * DIM];
    for (int r = wid; r < M_TILE; r += 8) {
        long row = base + r;
        if (row < N_FEAT) {
            const float4* fr = (const float4*)&ff[row * (long)DIM];
            float dot = 0.f, nr = 0.f;
            #pragma unroll
            for (int u = 0; u < 6; u++) {
                float4 a = fr[lid + 32 * u];
                float4 bq = qr[lid + 32 * u];
                dot = fmaf(a.x, bq.x, fmaf(a.y, bq.y, fmaf(a.z, bq.z, fmaf(a.w, bq.w, dot))));
                nr  = fmaf(a.x, a.x, fmaf(a.y, a.y, fmaf(a.z, a.z, fmaf(a.w, a.w, nr))));
            }
            #pragma unroll
            for (int off = 16; off >= 1; off >>= 1) {
                dot += __shfl_xor_sync(0xffffffffu, dot, off);
                nr  += __shfl_xor_sync(0xffffffffu, nr,  off);
            }
            if (lid == 0)
                insert5(dot * rsqrtf(nr), (int)row, tv, ti);
        }
    }
    if (lid == 0) {
        #pragma unroll
        for (int s = 0; s < TOPK; s++) { wtv[wid][s] = tv[s]; wti[wid][s] = ti[s]; }
    }
    __syncthreads();

    if (threadIdx.x == 0) {
        float mv[TOPK]; int mi[TOPK];
        #pragma unroll
        for (int s = 0; s < TOPK; s++) { mv[s] = -CUDART_INF_F; mi[s] = 0x7fffffff; }
        for (int w = 0; w < 8; w++)
            #pragma unroll
            for (int s = 0; s < TOPK; s++)
                insert5(wtv[w][s], wti[w][s], mv, mi);
        #pragma unroll
        for (int s = 0; s < TOPK; s++) {
            g_cv[b * TOPK + s] = mv[s];
            g_ci[b * TOPK + s] = mi[s];
        }
    }
}

// ---------------------------------------------------------------------------
// k4: per query, merge NSEL*5 = 40 candidates -> final top-5.
// ---------------------------------------------------------------------------
__global__ void final_kernel() {
    const int q = threadIdx.x;
    if (q >= NQ) return;
    float tv[TOPK]; int ti[TOPK];
    #pragma unroll
    for (int s = 0; s < TOPK; s++) { tv[s] = -CUDART_INF_F; ti[s] = 0x7fffffff; }
    for (int e = 0; e < NSEL * TOPK; e++)
        insert5(g_cv[q * NSEL * TOPK + e], g_ci[q * NSEL * TOPK + e], tv, ti);
    #pragma unroll
    for (int s = 0; s < TOPK; s++)
        g_top[q * TOPK + s] = ti[s];
}

// ---------------------------------------------------------------------------
// k5: gather + int->float (output dtype float32).
// ---------------------------------------------------------------------------
__global__ __launch_bounds__(128)
void gather_kernel(const int* __restrict__ data, float* __restrict__ out) {
    const int r = blockIdx.x;
    int idx = g_top[r];
    idx = (idx < 0) ? 0 : ((idx >= N_FEAT) ? N_FEAT - 1 : idx);
    const int4* src = (const int4*)&data[(size_t)idx * SEGLEN];
    float4* dst = (float4*)&out[(size_t)r * SEGLEN];
    for (int t = threadIdx.x; t < SEGLEN / 4; t += blockDim.x) {
        int4 v = src[t];
        dst[t] = make_float4((float)v.x, (float)v.y, (float)v.z, (float)v.w);
    }
}

// ---------------------------------------------------------------------------
extern "C" void kernel_launch(void* const* d_in, const int* in_sizes, int n_in,
                              void* d_out, int out_size) {
    (void)out_size;
    int i_ff = 0, i_dt = -1, i_qf = -1;
    for (int i = 1; i < n_in; i++)
        if ((unsigned)in_sizes[i] > (unsigned)in_sizes[i_ff]) i_ff = i;
    for (int i = 0; i < n_in; i++) {
        if (i == i_ff) continue;
        if (i_dt < 0 || (unsigned)in_sizes[i] > (unsigned)in_sizes[i_dt]) i_dt = i;
    }
    for (int i = 0; i < n_in; i++) {
        if (i == i_ff || i == i_dt) continue;
        if (i_qf < 0 || (unsigned)in_sizes[i] > (unsigned)in_sizes[i_qf]) i_qf = i;
    }
    const float* qf   = (const float*)d_in[i_qf >= 0 ? i_qf : 0];
    const float* ff   = (const float*)d_in[i_ff];
    const int*   data = (const int*)d_in[i_dt >= 0 ? i_dt : (n_in > 2 ? 2 : 0)];
    float* out = (float*)d_out;

    qconv_kernel<<<(NQ * DIM / 2 + 255) / 256, 256>>>(qf);
    const int S = (NBLK + 3) / 4;   // 977
    mma_score_kernel<<<S, 256>>>(ff, 0);
    mma_score_kernel<<<S, 256>>>(ff, S);
    mma_score_kernel<<<S, 256>>>(ff, 2 * S);
    mma_score_kernel<<<NBLK - 3 * S, 256>>>(ff, 3 * S);
    select_kernel<<<NQ, 256>>>();
    rescore_kernel<<<NQ * NSEL, 256>>>(qf, ff);
    final_kernel<<<1, NQ>>>();
    gather_kernel<<<NQ * TOPK, 128>>>(data, out);
}